// round 11
// baseline (speedup 1.0000x reference)
#include <cuda_runtime.h>
#include <math.h>

#define NN 2592
#define BB 128
#define LL 64
#define CC 16
#define CHO 64
#define GN 8            // n per CTA in routing kernels
#define NTILES (NN/GN)  // 324

// ---------------- scratch (device globals; no allocation) ----------------
__device__ float g_S0[BB * LL];                  // sum_n u_hat
__device__ float g_s1[BB * LL];
__device__ float g_s2[BB * LL];
__device__ float g_v0[BB * LL];                  // squash(S0/N)
__device__ float g_v1[BB * LL];                  // squash(s1)
__device__ float g_b1[NN];
__device__ float g_b2[NN];
__device__ float g_c1[NN];
__device__ float g_c2[NN];
__device__ float g_nrm2[(size_t)NN * BB];        // [n][b] : sum_l u_hat^2
__device__ unsigned g_cnt[4];                    // tickets: P1, A0, S0, A1

__device__ __forceinline__ float squashf(float s) {
    float sq = s * s;
    return s * fabsf(s) / (1.0f + sq);   // == sq*s/((1+sq)*sqrt(sq))
}

__device__ __forceinline__ void red_add_v4(float* p, float a, float b, float c, float d) {
    asm volatile("red.global.add.v4.f32 [%0], {%1, %2, %3, %4};"
                 :: "l"(p), "f"(a), "f"(b), "f"(c), "f"(d) : "memory");
}

// ---------------- K0: zero accumulators ----------------
__global__ void kzero() {
    int i = blockIdx.x * 256 + threadIdx.x;
    if (i < BB * LL) { g_S0[i] = 0.f; g_s1[i] = 0.f; g_s2[i] = 0.f; }
    if (i < 4) g_cnt[i] = 0u;
}

// ---- shared tile loaders (k1's proven pattern) ----
__device__ __forceinline__ void load_x_tile(float (*xs)[BB], const float* __restrict__ x,
                                            int n, int t) {
    int b = t & 127, half = t >> 7;
    const float4* xp = reinterpret_cast<const float4*>(x + ((size_t)b * NN + n) * CC) + half * 2;
    float4 a = xp[0], c4 = xp[1];
    int cb = half * 8;
    xs[cb + 0][b] = a.x;  xs[cb + 1][b] = a.y;  xs[cb + 2][b] = a.z;  xs[cb + 3][b] = a.w;
    xs[cb + 4][b] = c4.x; xs[cb + 5][b] = c4.y; xs[cb + 6][b] = c4.z; xs[cb + 7][b] = c4.w;
}
__device__ __forceinline__ void load_w_tile(float (*Ws)[LL], const float* __restrict__ W,
                                            int n, int t, float scale) {
    int l = t & 63, cq = t >> 6;
    const float4* wp = reinterpret_cast<const float4*>(W + ((size_t)n * LL + l) * CC + cq * 4);
    float4 a = wp[0];
    Ws[cq * 4 + 0][l] = a.x * scale; Ws[cq * 4 + 1][l] = a.y * scale;
    Ws[cq * 4 + 2][l] = a.z * scale; Ws[cq * 4 + 3][l] = a.w * scale;
}

// U-tile mainloop: acc[i][j] += sum_c xs[c][bbase+i] * Ws[c][lq*4+j]
#define U_MAINLOOP(ACCOP)                                                        \
    _Pragma("unroll")                                                            \
    for (int c = 0; c < CC; c++) {                                               \
        float4 xa = *reinterpret_cast<const float4*>(&xs[c][bbase]);             \
        float4 xb = *reinterpret_cast<const float4*>(&xs[c][bbase + 4]);         \
        float4 wv = *reinterpret_cast<const float4*>(&Ws[c][lq * 4]);            \
        float xr[8] = {xa.x, xa.y, xa.z, xa.w, xb.x, xb.y, xb.z, xb.w};          \
        float wr[4] = {wv.x, wv.y, wv.z, wv.w};                                  \
        _Pragma("unroll")                                                        \
        for (int i = 0; i < 8; i++)                                              \
            _Pragma("unroll")                                                    \
            for (int j = 0; j < 4; j++) ACCOP[i][j] += xr[i] * wr[j];            \
    }

// ---------------- kP1: S0 + nrm2 (no u_hat store); tail: v0 ----------------
__global__ void __launch_bounds__(256) kP1(const float* __restrict__ x,
                                           const float* __restrict__ W) {
    __shared__ __align__(16) float xs[CC][BB];
    __shared__ __align__(16) float Ws[CC][LL];
    __shared__ float ps[CC][BB + 1];
    __shared__ unsigned s_tk;
    __shared__ float sred[8];

    int t = threadIdx.x;
    int n0 = blockIdx.x * GN;
    int bg = t >> 4, lq = t & 15, bbase = bg * 8;
    int lane = t & 31, wid = t >> 5;

    float s_acc[8][4];
#pragma unroll
    for (int i = 0; i < 8; i++)
#pragma unroll
        for (int j = 0; j < 4; j++) s_acc[i][j] = 0.f;

#pragma unroll 1
    for (int nn = 0; nn < GN; nn++) {
        int n = n0 + nn;
        load_x_tile(xs, x, n, t);
        load_w_tile(Ws, W, n, t, 1.0f);
        __syncthreads();

        float acc[8][4];
#pragma unroll
        for (int i = 0; i < 8; i++)
#pragma unroll
            for (int j = 0; j < 4; j++) acc[i][j] = 0.f;
        U_MAINLOOP(acc)

#pragma unroll
        for (int i = 0; i < 8; i++) {
            ps[lq][bbase + i] = acc[i][0] * acc[i][0] + acc[i][1] * acc[i][1] +
                                acc[i][2] * acc[i][2] + acc[i][3] * acc[i][3];
            s_acc[i][0] += acc[i][0]; s_acc[i][1] += acc[i][1];
            s_acc[i][2] += acc[i][2]; s_acc[i][3] += acc[i][3];
        }
        __syncthreads();
        if (t < BB) {
            float nr = 0.f;
#pragma unroll
            for (int q = 0; q < 16; q++) nr += ps[q][t];
            g_nrm2[(size_t)n * BB + t] = nr;
        }
        __syncthreads();
    }

#pragma unroll
    for (int i = 0; i < 8; i++)
        red_add_v4(&g_S0[(bbase + i) * LL + lq * 4],
                   s_acc[i][0], s_acc[i][1], s_acc[i][2], s_acc[i][3]);

    if (t == 0) { __threadfence(); s_tk = atomicAdd(&g_cnt[0], 1u); }
    __syncthreads();
    if (s_tk != NTILES - 1) return;
    __threadfence();
    (void)lane; (void)wid; (void)sred;
    for (int i = t; i < BB * LL; i += 256)
        g_v0[i] = squashf(__ldcg(&g_S0[i]) * (1.0f / NN));
}

// ---------------- kA: b[n] = (1/B) sum_{b,l} U[b,l] * v[b,l]; tail: softmax ----------------
__global__ void __launch_bounds__(256) kA(const float* __restrict__ x,
                                          const float* __restrict__ W, int mode) {
    __shared__ __align__(16) float xs[CC][BB];
    __shared__ __align__(16) float Ws[CC][LL];
    __shared__ __align__(16) float vsm[BB * 68];   // v, padded rows (34.8 KB)
    __shared__ float wsum[8][GN];
    __shared__ float s8[GN];
    __shared__ float sred[8];
    __shared__ unsigned s_tk;

    const float* vsrc = mode ? g_v1 : g_v0;
    float* bOut = mode ? g_b2 : g_b1;
    float* cOut = mode ? g_c2 : g_c1;

    int t = threadIdx.x;
    int lane = t & 31, wid = t >> 5;
    int n0 = blockIdx.x * GN;
    int bg = t >> 4, lq = t & 15, bbase = bg * 8;

    for (int i = t; i < BB * LL; i += 256)
        vsm[(i >> 6) * 68 + (i & 63)] = vsrc[i];
    __syncthreads();

#pragma unroll 1
    for (int nn = 0; nn < GN; nn++) {
        int n = n0 + nn;
        load_x_tile(xs, x, n, t);
        load_w_tile(Ws, W, n, t, 1.0f);
        __syncthreads();

        float acc[8][4];
#pragma unroll
        for (int i = 0; i < 8; i++)
#pragma unroll
            for (int j = 0; j < 4; j++) acc[i][j] = 0.f;
        U_MAINLOOP(acc)

        float part = 0.f;
#pragma unroll
        for (int i = 0; i < 8; i++) {
            float4 vv = *reinterpret_cast<const float4*>(&vsm[(bbase + i) * 68 + lq * 4]);
            part += acc[i][0] * vv.x + acc[i][1] * vv.y + acc[i][2] * vv.z + acc[i][3] * vv.w;
        }
#pragma unroll
        for (int off = 16; off; off >>= 1) part += __shfl_xor_sync(0xffffffffu, part, off);
        if (lane == 0) wsum[wid][nn] = part;
        __syncthreads();   // wsum visible + xs/Ws reuse safe
    }

    if (t < GN) {
        float sum = 0.f;
#pragma unroll
        for (int w = 0; w < 8; w++) sum += wsum[w][t];
        sum *= (1.0f / BB);
        if (mode) sum += g_b1[n0 + t];   // b2 = b1 + mean
        s8[t] = sum;
    }
    __syncthreads();
    if (t == 0) {
#pragma unroll
        for (int i = 0; i < GN; i++) bOut[n0 + i] = s8[i];
        __threadfence();
        s_tk = atomicAdd(&g_cnt[mode ? 3 : 1], 1u);
    }
    __syncthreads();
    if (s_tk != NTILES - 1) return;

    // ---- last CTA: c = softmax(bOut) ----
    __threadfence();
    float m = -3.0e38f;
    for (int i = t; i < NN; i += 256) m = fmaxf(m, __ldcg(&bOut[i]));
#pragma unroll
    for (int off = 16; off; off >>= 1) m = fmaxf(m, __shfl_xor_sync(0xffffffffu, m, off));
    if (lane == 0) sred[wid] = m;
    __syncthreads();
    float mx = sred[0];
#pragma unroll
    for (int q = 1; q < 8; q++) mx = fmaxf(mx, sred[q]);
    __syncthreads();

    float sm = 0.f;
    for (int i = t; i < NN; i += 256) sm += __expf(__ldcg(&bOut[i]) - mx);
#pragma unroll
    for (int off = 16; off; off >>= 1) sm += __shfl_xor_sync(0xffffffffu, sm, off);
    if (lane == 0) sred[wid] = sm;
    __syncthreads();
    float inv = 1.0f / (sred[0] + sred[1] + sred[2] + sred[3] +
                        sred[4] + sred[5] + sred[6] + sred[7]);
    for (int i = t; i < NN; i += 256) cOut[i] = __expf(__ldcg(&bOut[i]) - mx) * inv;
}

// ---------------- kS: sOut += sum_n c_n * U_n  (Ws pre-scaled by c_n); mode0 tail: v1 ----------------
__global__ void __launch_bounds__(256) kS(const float* __restrict__ x,
                                          const float* __restrict__ W, int mode) {
    __shared__ __align__(16) float xs[CC][BB];
    __shared__ __align__(16) float Ws[CC][LL];
    __shared__ float cs[GN];
    __shared__ unsigned s_tk;

    const float* cIn = mode ? g_c2 : g_c1;
    float* sOut = mode ? g_s2 : g_s1;

    int t = threadIdx.x;
    int n0 = blockIdx.x * GN;
    int bg = t >> 4, lq = t & 15, bbase = bg * 8;

    if (t < GN) cs[t] = cIn[n0 + t];
    __syncthreads();

    float acc[8][4];
#pragma unroll
    for (int i = 0; i < 8; i++)
#pragma unroll
        for (int j = 0; j < 4; j++) acc[i][j] = 0.f;

#pragma unroll 1
    for (int nn = 0; nn < GN; nn++) {
        int n = n0 + nn;
        load_x_tile(xs, x, n, t);
        load_w_tile(Ws, W, n, t, cs[nn]);   // fold c_n into W tile
        __syncthreads();
        U_MAINLOOP(acc)                      // acc accumulates across nn
        __syncthreads();
    }

#pragma unroll
    for (int i = 0; i < 8; i++)
        red_add_v4(&sOut[(bbase + i) * LL + lq * 4],
                   acc[i][0], acc[i][1], acc[i][2], acc[i][3]);

    if (mode == 0) {
        if (t == 0) { __threadfence(); s_tk = atomicAdd(&g_cnt[2], 1u); }
        __syncthreads();
        if (s_tk != NTILES - 1) return;
        __threadfence();
        for (int i = t; i < BB * LL; i += 256)
            g_v1[i] = squashf(__ldcg(&g_s1[i]));
    }
}

// ---------------- K6: v_j output + ConvTranspose2d ----------------
__global__ void __launch_bounds__(256) k6_out(const float* __restrict__ cw,
                                              const float* __restrict__ cb,
                                              float* __restrict__ out) {
    int t = threadIdx.x;
    if (blockIdx.x >= 2048) {
        int idx = (blockIdx.x - 2048) * 256 + t;   // 32*256 = 8192
        out[idx] = squashf(g_s2[idx]);
        return;
    }
    int b = blockIdx.x >> 4, oh = blockIdx.x & 15;
    __shared__ float ws[32][64][2];
    __shared__ float un[32][9];
    __shared__ float bias[CHO];

    int kh = oh & 1;
    int ih = (oh + kh) >> 1;

    for (int i = t; i < 32 * 64 * 2; i += 256) {
        int ic = i >> 7, r = i & 127, oc = r >> 1, j = r & 1;
        ws[ic][oc][j] = cw[ic * 256 + oc * 4 + (1 - kh) * 2 + j];
    }
    for (int i = t; i < 288; i += 256) {
        int ic = i / 9, iw = i - ic * 9;
        int n = ic * 81 + ih * 9 + iw;
        un[ic][iw] = g_c2[n] * sqrtf(g_nrm2[(size_t)n * BB + b]);
    }
    if (t < CHO) bias[t] = cb[t];
    __syncthreads();

    int ow = t & 15, ocg = t >> 4;
    int kw = ow & 1;
    int iw = (ow + kw) >> 1;
    int j = 1 - kw;
    size_t obase = 8192 + (((size_t)b * CHO) * 16 + oh) * 16 + ow;
#pragma unroll
    for (int q = 0; q < 4; q++) {
        int oc = ocg * 4 + q;
        float acc = bias[oc];
#pragma unroll
        for (int ic = 0; ic < 32; ic++) acc += un[ic][iw] * ws[ic][oc][j];
        out[obase + (size_t)oc * 256] = acc;
    }
}

// ---------------- launch ----------------
extern "C" void kernel_launch(void* const* d_in, const int* in_sizes, int n_in,
                              void* d_out, int out_size) {
    const float* x  = (const float*)d_in[0];   // (128, 2592, 16)
    const float* W  = (const float*)d_in[1];   // (1, 2592, 1, 64, 16)
    const float* cw = (const float*)d_in[2];   // (32, 64, 2, 2)
    const float* cb = (const float*)d_in[3];   // (64,)
    float* out = (float*)d_out;                // 8192 (v_j) + 2097152 (out_img)

    kzero<<<32, 256>>>();
    kP1<<<NTILES, 256>>>(x, W);      // S0 + nrm2; tail: v0 = squash(S0/N)
    kA<<<NTILES, 256>>>(x, W, 0);    // b1 = mean<U, v0>; tail: c1 = softmax(b1)
    kS<<<NTILES, 256>>>(x, W, 0);    // s1 = sum c1*U; tail: v1 = squash(s1)
    kA<<<NTILES, 256>>>(x, W, 1);    // b2 = b1 + mean<U, v1>; tail: c2 = softmax(b2)
    kS<<<NTILES, 256>>>(x, W, 1);    // s2 = sum c2*U
    k6_out<<<2080, 256>>>(cw, cb, out);  // v_j = squash(s2); ConvT -> out_img
}

// round 12
// speedup vs baseline: 1.7361x; 1.7361x over previous
#include <cuda_runtime.h>
#include <cuda_fp16.h>
#include <math.h>

#define NN 2592
#define BB 128
#define LL 64
#define CC 16
#define CHO 64

// ---------------- scratch (device globals; no allocation) ----------------
__device__ __half g_uhatH[(size_t)NN * BB * LL]; // [n][b][l]  ~42.5 MB fp16
__device__ float g_S0[BB * LL];                  // sum_n u_hat (exact fp32)
__device__ float g_s1[BB * LL];
__device__ float g_s2[BB * LL];
__device__ float g_b1[NN];
__device__ float g_b2[NN];
__device__ float g_c1[NN];
__device__ float g_c2[NN];
__device__ float g_nrm2[(size_t)NN * BB];        // [n][b] : sum_l u_hat^2 (exact fp32)
__device__ unsigned g_cnt[2];                    // a-pass completion tickets

struct alignas(8) h4pack { __half2 a, b; };

__device__ __forceinline__ float squashf(float s) {
    float sq = s * s;
    return s * fabsf(s) / (1.0f + sq);   // == sq*s/((1+sq)*sqrt(sq))
}

__device__ __forceinline__ void red_add_v4(float* p, float a, float b, float c, float d) {
    asm volatile("red.global.add.v4.f32 [%0], {%1, %2, %3, %4};"
                 :: "l"(p), "f"(a), "f"(b), "f"(c), "f"(d) : "memory");
}

// ---------------- K0: zero accumulators ----------------
__global__ void kzero() {
    int i = blockIdx.x * 256 + threadIdx.x;
    if (i < BB * LL) { g_S0[i] = 0.f; g_s1[i] = 0.f; g_s2[i] = 0.f; }
    if (i < NN) { g_b1[i] = 0.f; g_b2[i] = 0.f; }
    if (i < 2) g_cnt[i] = 0u;
}

// ---------------- K1: u_hat(fp16) + S0 (red.v4, fp32) + nrm2 (fp32) ---- R6 body ----
// grid 648 (4 n per CTA), 256 threads. Per n: (128b x 64l) = x[:,n,:](128x16) @ W[n]^T(16x64)
__global__ void __launch_bounds__(256) k1_uhat(const float* __restrict__ x,
                                               const float* __restrict__ W) {
    __shared__ float xs[CC][BB];
    __shared__ float Ws[CC][LL];
    __shared__ float ps[CC][BB + 1];

    int t = threadIdx.x;
    int n0 = blockIdx.x * 4;
    int bg = t >> 4, lq = t & 15;
    int bbase = bg * 8;

    float s_acc[8][4];
#pragma unroll
    for (int i = 0; i < 8; i++)
#pragma unroll
        for (int j = 0; j < 4; j++) s_acc[i][j] = 0.f;

#pragma unroll 1
    for (int nn = 0; nn < 4; nn++) {
        int n = n0 + nn;
        {   // x[:, n, :] -> xs[c][b]
            int b = t & 127, half = t >> 7;
            const float4* xp = reinterpret_cast<const float4*>(x + ((size_t)b * NN + n) * CC) + half * 2;
            float4 a = xp[0], c4 = xp[1];
            int cb = half * 8;
            xs[cb + 0][b] = a.x;  xs[cb + 1][b] = a.y;  xs[cb + 2][b] = a.z;  xs[cb + 3][b] = a.w;
            xs[cb + 4][b] = c4.x; xs[cb + 5][b] = c4.y; xs[cb + 6][b] = c4.z; xs[cb + 7][b] = c4.w;
        }
        {   // W[n] -> Ws[c][l]
            int l = t & 63, cq = t >> 6;
            const float4* wp = reinterpret_cast<const float4*>(W + ((size_t)n * LL + l) * CC + cq * 4);
            float4 a = wp[0];
            Ws[cq * 4 + 0][l] = a.x; Ws[cq * 4 + 1][l] = a.y;
            Ws[cq * 4 + 2][l] = a.z; Ws[cq * 4 + 3][l] = a.w;
        }
        __syncthreads();

        float acc[8][4];
#pragma unroll
        for (int i = 0; i < 8; i++)
#pragma unroll
            for (int j = 0; j < 4; j++) acc[i][j] = 0.f;

#pragma unroll
        for (int c = 0; c < CC; c++) {
            float4 xa = *reinterpret_cast<const float4*>(&xs[c][bbase]);
            float4 xb = *reinterpret_cast<const float4*>(&xs[c][bbase + 4]);
            float4 wv = *reinterpret_cast<const float4*>(&Ws[c][lq * 4]);
            float xr[8] = {xa.x, xa.y, xa.z, xa.w, xb.x, xb.y, xb.z, xb.w};
            float wr[4] = {wv.x, wv.y, wv.z, wv.w};
#pragma unroll
            for (int i = 0; i < 8; i++)
#pragma unroll
                for (int j = 0; j < 4; j++) acc[i][j] += xr[i] * wr[j];
        }

        __half* ub = g_uhatH + (size_t)n * BB * LL;
#pragma unroll
        for (int i = 0; i < 8; i++) {
            int b = bbase + i;
            h4pack pk;
            pk.a = __floats2half2_rn(acc[i][0], acc[i][1]);
            pk.b = __floats2half2_rn(acc[i][2], acc[i][3]);
            *reinterpret_cast<h4pack*>(ub + b * LL + lq * 4) = pk;
            ps[lq][b] = acc[i][0] * acc[i][0] + acc[i][1] * acc[i][1] +
                        acc[i][2] * acc[i][2] + acc[i][3] * acc[i][3];
            s_acc[i][0] += acc[i][0]; s_acc[i][1] += acc[i][1];
            s_acc[i][2] += acc[i][2]; s_acc[i][3] += acc[i][3];
        }
        __syncthreads();
        if (t < BB) {
            float nr = 0.f;
#pragma unroll
            for (int q = 0; q < 16; q++) nr += ps[q][t];
            g_nrm2[(size_t)n * BB + t] = nr;
        }
        __syncthreads();
    }

#pragma unroll
    for (int i = 0; i < 8; i++)
        red_add_v4(&g_S0[(bbase + i) * LL + lq * 4],
                   s_acc[i][0], s_acc[i][1], s_acc[i][2], s_acc[i][3]);
}

// ---------------- a-pass: R6 body + R10 ticket-tail softmax ----------------
// b_out[n] += (1/B) * sum_{b in tile} <u_hat[b,n,:], v[b,:]>,  v = squash(sIn*scale)
// grid 1296 = 324 n-tiles (8 n) x 4 b-tiles (32 b). warp w handles n0+w over 32 b.
// Last-ticket CTA computes c = softmax(b_out) inline (no extra launch).
__global__ void __launch_bounds__(256) k_apass(int mode) {
    const float* sIn = (mode == 0) ? g_S0 : g_s1;
    float sscale = (mode == 0) ? (1.0f / NN) : 1.0f;
    float* bOut = (mode == 0) ? g_b1 : g_b2;
    float* cOut = (mode == 0) ? g_c1 : g_c2;

    __shared__ float vs[32 * LL];   // 8 KB
    __shared__ float s8[8];
    __shared__ float sred[8];
    __shared__ unsigned s_tk;

    int t = threadIdx.x;
    int w = t >> 5, lane = t & 31;
    int nt = blockIdx.x >> 2, bq = blockIdx.x & 3;
    int n0 = nt * 8, b0 = bq * 32;

    {   // vs = squash(sIn[b0..b0+32, :]*scale)  (R6 float4 path)
        const float4* sp = reinterpret_cast<const float4*>(sIn) + b0 * (LL / 4);
        float4* vp4 = reinterpret_cast<float4*>(vs);
        for (int i = t; i < 32 * LL / 4; i += 256) {
            float4 a = sp[i];
            vp4[i] = make_float4(squashf(a.x * sscale), squashf(a.y * sscale),
                                 squashf(a.z * sscale), squashf(a.w * sscale));
        }
    }
    __syncthreads();

    int n = n0 + w;
    const __half2* up = reinterpret_cast<const __half2*>(g_uhatH + ((size_t)n * BB + b0) * LL) + lane;
    const float2* vp = reinterpret_cast<const float2*>(vs) + lane;
    float acc = 0.f;
#pragma unroll 8
    for (int b = 0; b < 32; b++) {
        float2 u = __half22float2(up[b * 32]);
        float2 vv = vp[b * 32];
        acc += u.x * vv.x + u.y * vv.y;
    }
#pragma unroll
    for (int off = 16; off; off >>= 1) acc += __shfl_xor_sync(0xffffffffu, acc, off);
    if (lane == 0) {
        acc *= (1.0f / BB);
        if (mode == 1 && bq == 0) acc += g_b1[n];   // b2 = b1 + mean
        s8[w] = acc;
    }
    __syncthreads();

    // thread 0 is the sole bOut writer -> its fence orders all 8 adds before the ticket
    if (t == 0) {
#pragma unroll
        for (int i = 0; i < 8; i++) atomicAdd(&bOut[n0 + i], s8[i]);
        __threadfence();
        s_tk = atomicAdd(&g_cnt[mode], 1u);
    }
    __syncthreads();
    if (s_tk != 1295u) return;

    // ---- last CTA: softmax over bOut -> cOut ----
    __threadfence();   // acquire: see all CTAs' bOut atomics
    float m = -3.0e38f;
    for (int i = t; i < NN; i += 256) m = fmaxf(m, __ldcg(&bOut[i]));
#pragma unroll
    for (int off = 16; off; off >>= 1) m = fmaxf(m, __shfl_xor_sync(0xffffffffu, m, off));
    if (lane == 0) sred[w] = m;
    __syncthreads();
    float mx = sred[0];
#pragma unroll
    for (int q = 1; q < 8; q++) mx = fmaxf(mx, sred[q]);
    __syncthreads();

    float sm = 0.f;
    for (int i = t; i < NN; i += 256) sm += __expf(__ldcg(&bOut[i]) - mx);
#pragma unroll
    for (int off = 16; off; off >>= 1) sm += __shfl_xor_sync(0xffffffffu, sm, off);
    if (lane == 0) sred[w] = sm;
    __syncthreads();
    float inv = 1.0f / (sred[0] + sred[1] + sred[2] + sred[3] +
                        sred[4] + sred[5] + sred[6] + sred[7]);
    for (int i = t; i < NN; i += 256) cOut[i] = __expf(__ldcg(&bOut[i]) - mx) * inv;
}

// ---------------- s-pass (R10, measured 15.6us) ----------------
// sOut[b,l] += sum_{n in tile} c[n]*u_hat[n,b,l]; c precomputed in a-pass tail.
// grid 1296 = 324 n-tiles (8 n) x 4 b-tiles (32 b).
__global__ void __launch_bounds__(256) k_spass(int mode) {
    const float* cIn = (mode == 0) ? g_c1 : g_c2;
    float* sOut = (mode == 0) ? g_s1 : g_s2;

    __shared__ float cs[8];
    int t = threadIdx.x;
    int nt = blockIdx.x >> 2, bq = blockIdx.x & 3;
    int n0 = nt * 8, b0 = bq * 32;

    if (t < 8) cs[t] = cIn[n0 + t];
    __syncthreads();

    // thread -> (bl = t>>3 in [0,32), l4 = t&7): one uint4 (8 fp16) per n
    int bl = t >> 3, l4 = t & 7;
    float a0 = 0.f, a1 = 0.f, a2 = 0.f, a3 = 0.f;
    float a4 = 0.f, a5 = 0.f, a6 = 0.f, a7 = 0.f;
#pragma unroll
    for (int nn = 0; nn < 8; nn++) {
        float cv = cs[nn];
        const uint4* p = reinterpret_cast<const uint4*>(
            g_uhatH + ((size_t)(n0 + nn) * BB + b0 + bl) * LL);
        uint4 q = p[l4];
        float2 f0 = __half22float2(*reinterpret_cast<const __half2*>(&q.x));
        float2 f1 = __half22float2(*reinterpret_cast<const __half2*>(&q.y));
        float2 f2 = __half22float2(*reinterpret_cast<const __half2*>(&q.z));
        float2 f3 = __half22float2(*reinterpret_cast<const __half2*>(&q.w));
        a0 += cv * f0.x; a1 += cv * f0.y; a2 += cv * f1.x; a3 += cv * f1.y;
        a4 += cv * f2.x; a5 += cv * f2.y; a6 += cv * f3.x; a7 += cv * f3.y;
    }
    float* dst = sOut + (b0 + bl) * LL + l4 * 8;
    red_add_v4(dst, a0, a1, a2, a3);
    red_add_v4(dst + 4, a4, a5, a6, a7);
}

// ---------------- K6: v_j output + ConvTranspose2d ----------------
__global__ void __launch_bounds__(256) k6_out(const float* __restrict__ cw,
                                              const float* __restrict__ cb,
                                              float* __restrict__ out) {
    int t = threadIdx.x;
    if (blockIdx.x >= 2048) {
        int idx = (blockIdx.x - 2048) * 256 + t;   // 32*256 = 8192
        out[idx] = squashf(g_s2[idx]);
        return;
    }
    int b = blockIdx.x >> 4, oh = blockIdx.x & 15;
    __shared__ float ws[32][64][2];
    __shared__ float un[32][9];
    __shared__ float bias[CHO];

    int kh = oh & 1;
    int ih = (oh + kh) >> 1;

    for (int i = t; i < 32 * 64 * 2; i += 256) {
        int ic = i >> 7, r = i & 127, oc = r >> 1, j = r & 1;
        ws[ic][oc][j] = cw[ic * 256 + oc * 4 + (1 - kh) * 2 + j];
    }
    for (int i = t; i < 288; i += 256) {
        int ic = i / 9, iw = i - ic * 9;
        int n = ic * 81 + ih * 9 + iw;
        un[ic][iw] = g_c2[n] * sqrtf(g_nrm2[(size_t)n * BB + b]);
    }
    if (t < CHO) bias[t] = cb[t];
    __syncthreads();

    int ow = t & 15, ocg = t >> 4;
    int kw = ow & 1;
    int iw = (ow + kw) >> 1;
    int j = 1 - kw;
    size_t obase = 8192 + (((size_t)b * CHO) * 16 + oh) * 16 + ow;
#pragma unroll
    for (int q = 0; q < 4; q++) {
        int oc = ocg * 4 + q;
        float acc = bias[oc];
#pragma unroll
        for (int ic = 0; ic < 32; ic++) acc += un[ic][iw] * ws[ic][oc][j];
        out[obase + (size_t)oc * 256] = acc;
    }
}

// ---------------- launch ----------------
extern "C" void kernel_launch(void* const* d_in, const int* in_sizes, int n_in,
                              void* d_out, int out_size) {
    const float* x  = (const float*)d_in[0];   // (128, 2592, 16)
    const float* W  = (const float*)d_in[1];   // (1, 2592, 1, 64, 16)
    const float* cw = (const float*)d_in[2];   // (32, 64, 2, 2)
    const float* cb = (const float*)d_in[3];   // (64,)
    float* out = (float*)d_out;                // 8192 (v_j) + 2097152 (out_img)

    kzero<<<32, 256>>>();
    k1_uhat<<<648, 256>>>(x, W);    // u_hat(fp16) + S0 + nrm2
    k_apass<<<1296, 256>>>(0);      // b1 = mean_b <u_hat, squash(S0/N)>; tail: c1=softmax(b1)
    k_spass<<<1296, 256>>>(0);      // s1 = sum c1*u_hat
    k_apass<<<1296, 256>>>(1);      // b2 = b1 + mean_b <u_hat, squash(s1)>; tail: c2=softmax(b2)
    k_spass<<<1296, 256>>>(1);      // s2 = sum c2*u_hat
    k6_out<<<2080, 256>>>(cw, cb, out);  // v_j = squash(s2); ConvT -> out_img
}